// round 8
// baseline (speedup 1.0000x reference)
#include <cuda_runtime.h>
#include <cuda_fp16.h>
#include <cstdint>

// Problem constants
#define B_ 4
#define N_ 4096
#define D_ 512
#define K_ 32
#define TILES 32            // N_/128
#define PAIRS 528           // TILES*(TILES+1)/2

// Scratch (device globals — no runtime allocation allowed)
__device__ __align__(128) __half g_h[(size_t)B_ * N_ * D_];           // 16 MB
__device__ __align__(128) __half g_l[(size_t)B_ * N_ * D_];           // 16 MB
__device__ __align__(128) float g_sim[(size_t)B_ * N_ * N_];          // 268 MB

// ---------------------------------------------------------------------------
// Portable PTX helpers (compute_103-safe)
// ---------------------------------------------------------------------------
__device__ __forceinline__ uint32_t smem_u32(const void* p) {
    uint32_t a;
    asm("{ .reg .u64 t; cvta.to.shared.u64 t, %1; cvt.u32.u64 %0, t; }"
        : "=r"(a) : "l"(p));
    return a;
}

#define SWZ(off) ((off) ^ (((off) >> 3) & 0x70))

#define CP_ASYNC16(dst_u32, src_ptr) \
    asm volatile("cp.async.cg.shared.global [%0], [%1], 16;" \
                 :: "r"(dst_u32), "l"(src_ptr) : "memory")
#define CP_COMMIT() asm volatile("cp.async.commit_group;" ::: "memory")
#define CP_WAIT(n)  asm volatile("cp.async.wait_group %0;" :: "n"(n) : "memory")

#define LDSM_X4(r0, r1, r2, r3, addr) \
    asm volatile("ldmatrix.sync.aligned.m8n8.x4.shared.b16 {%0,%1,%2,%3}, [%4];" \
                 : "=r"(r0), "=r"(r1), "=r"(r2), "=r"(r3) : "r"(addr))

#define MMA16816F16(c, a, b) \
    asm volatile("mma.sync.aligned.m16n8k16.row.col.f32.f16.f16.f32 " \
                 "{%0,%1,%2,%3}, {%4,%5,%6,%7}, {%8,%9}, {%0,%1,%2,%3};" \
                 : "+f"((c)[0]), "+f"((c)[1]), "+f"((c)[2]), "+f"((c)[3]) \
                 : "r"((a)[0]), "r"((a)[1]), "r"((a)[2]), "r"((a)[3]), \
                   "r"((b)[0]), "r"((b)[1]))

// ---------------------------------------------------------------------------
// Kernel 1: row L2-normalization + fp16 2-limb split (h + l ~ 22+ bits).
// ---------------------------------------------------------------------------
__global__ void __launch_bounds__(128) normalize_kernel(const float* __restrict__ x) {
    int row = blockIdx.x;
    const float* xr = x + (size_t)row * D_;
    int t = threadIdx.x;

    float4 v = ((const float4*)xr)[t];
    float ss = v.x * v.x + v.y * v.y + v.z * v.z + v.w * v.w;
    #pragma unroll
    for (int o = 16; o; o >>= 1) ss += __shfl_xor_sync(0xffffffffu, ss, o);

    __shared__ float wsum[4];
    if ((t & 31) == 0) wsum[t >> 5] = ss;
    __syncthreads();
    float total = wsum[0] + wsum[1] + wsum[2] + wsum[3];
    float scale = 1.0f / fmaxf(sqrtf(total), 1e-12f);

    float xn[4] = {v.x * scale, v.y * scale, v.z * scale, v.w * scale};
    unsigned short hs[4], ls[4];
    #pragma unroll
    for (int q = 0; q < 4; q++) {
        __half h = __float2half_rn(xn[q]);
        float r1 = xn[q] - __half2float(h);
        __half l = __float2half_rn(r1);
        hs[q] = __half_as_ushort(h);
        ls[q] = __half_as_ushort(l);
    }
    uint2 hp, lp;
    hp.x = (uint32_t)hs[0] | ((uint32_t)hs[1] << 16);
    hp.y = (uint32_t)hs[2] | ((uint32_t)hs[3] << 16);
    lp.x = (uint32_t)ls[0] | ((uint32_t)ls[1] << 16);
    lp.y = (uint32_t)ls[2] | ((uint32_t)ls[3] << 16);
    ((uint2*)(g_h + (size_t)row * D_))[t] = hp;
    ((uint2*)(g_l + (size_t)row * D_))[t] = lp;
}

// ---------------------------------------------------------------------------
// Kernel 2: symmetric batched GEMM, fp16 2-limb 3-pass on mma.sync (HMMA).
// EXACT R6 pipeline (measured best): issue load(k+1), CP_WAIT(1), sync,
// compute(k), sync. g_sim bitwise identical to R6.
// ---------------------------------------------------------------------------
#define CHUNK_BYTES 16384                 // 128 rows x 64 fp16 (128B/row)
#define BUF_BYTES   (4 * CHUNK_BYTES)     // Ah, Al, Bh, Bl = 64 KB
#define SMEM_TOTAL  (2 * BUF_BYTES)       // 128 KB; transpose area reuses it

__global__ void __launch_bounds__(512, 1) gemm_hmma_kernel() {
    extern __shared__ __align__(1024) char smem[];
    uint32_t sbase = smem_u32(smem);
    int tid = threadIdx.x;
    int wid = tid >> 5;
    int lane = tid & 31;

    int bidx = blockIdx.x;
    int b = bidx / PAIRS;
    int u = bidx % PAIRS;
    int ti = 0;
    while (u >= TILES - ti) { u -= TILES - ti; ti++; }
    int tj = ti + u;                      // tj >= ti

    size_t aoff = ((size_t)b * N_ + (size_t)ti * 128) * D_;
    size_t boff = ((size_t)b * N_ + (size_t)tj * 128) * D_;
    const __half* srcs[4] = {
        g_h + aoff, g_l + aoff,           // A limbs
        g_h + boff, g_l + boff            // B limbs
    };

    int wm = wid & 3;                     // 4 warps in M (32 rows each)
    int wn = wid >> 2;                    // 4 warps in N (32 cols each)

    float acc[2][4][4];
    #pragma unroll
    for (int mt = 0; mt < 2; mt++)
        #pragma unroll
        for (int nt = 0; nt < 4; nt++)
            #pragma unroll
            for (int q = 0; q < 4; q++) acc[mt][nt][q] = 0.0f;

    auto load_chunk = [&](int kc, int buf) {
        uint32_t bufoff = sbase + buf * BUF_BYTES;
        #pragma unroll
        for (int tile = 0; tile < 4; ++tile) {
            #pragma unroll
            for (int q = 0; q < 2; ++q) {
                int uu = q * 512 + tid;           // 0..1023
                int row = uu >> 3;
                int seg = uu & 7;
                const __half* src = srcs[tile] + (size_t)row * D_ + kc * 64 + seg * 8;
                uint32_t dst = bufoff + tile * CHUNK_BYTES + SWZ(row * 128 + seg * 16);
                CP_ASYNC16(dst, src);
            }
        }
    };

    int lr = lane & 15;
    int lc = (lane >> 4) * 16;

    auto compute_chunk = [&](int buf) {
        uint32_t aH = sbase + buf * BUF_BYTES;
        uint32_t aL = aH + CHUNK_BYTES;
        uint32_t bH = aH + 2 * CHUNK_BYTES;
        uint32_t bL = aH + 3 * CHUNK_BYTES;
        #pragma unroll
        for (int ks = 0; ks < 4; ++ks) {
            int kb = ks * 32;
            uint32_t ah[2][4], al[2][4];
            uint32_t bh[4][2], bl[4][2];
            #pragma unroll
            for (int mt = 0; mt < 2; ++mt) {
                int row = wm * 32 + mt * 16 + lr;
                uint32_t off = SWZ(row * 128 + kb + lc);
                LDSM_X4(ah[mt][0], ah[mt][1], ah[mt][2], ah[mt][3], aH + off);
                LDSM_X4(al[mt][0], al[mt][1], al[mt][2], al[mt][3], aL + off);
            }
            #pragma unroll
            for (int h = 0; h < 2; ++h) {
                int row = wn * 32 + h * 16 + lr;
                uint32_t off = SWZ(row * 128 + kb + lc);
                uint32_t r0, r1, r2, r3;
                LDSM_X4(r0, r1, r2, r3, bH + off);
                bh[2 * h + 0][0] = r0; bh[2 * h + 0][1] = r2;
                bh[2 * h + 1][0] = r1; bh[2 * h + 1][1] = r3;
                LDSM_X4(r0, r1, r2, r3, bL + off);
                bl[2 * h + 0][0] = r0; bl[2 * h + 0][1] = r2;
                bl[2 * h + 1][0] = r1; bl[2 * h + 1][1] = r3;
            }
            #pragma unroll
            for (int mt = 0; mt < 2; ++mt)
                #pragma unroll
                for (int nt = 0; nt < 4; ++nt) {
                    MMA16816F16(acc[mt][nt], ah[mt], bh[nt]);   // hh
                    MMA16816F16(acc[mt][nt], ah[mt], bl[nt]);   // hl
                    MMA16816F16(acc[mt][nt], al[mt], bh[nt]);   // lh
                }
        }
    };

    // ---- pipelined main loop over 8 K-chunks (R6 structure) ----
    const int NCHUNK = D_ / 64;
    load_chunk(0, 0); CP_COMMIT();
    for (int kc = 0; kc < NCHUNK; ++kc) {
        if (kc + 1 < NCHUNK) {
            load_chunk(kc + 1, (kc + 1) & 1); CP_COMMIT();
            CP_WAIT(1);
        } else {
            CP_WAIT(0);
        }
        __syncthreads();
        compute_chunk(kc & 1);
        __syncthreads();                  // before next load overwrites other buf
    }

    // ---- epilogue: direct tile (coalesced float2 per fragment row) ----
    float* C = g_sim + (size_t)b * N_ * N_;
    int r0 = ti * 128 + wm * 32 + (lane >> 2);
    int c0 = tj * 128 + wn * 32 + (lane & 3) * 2;
    #pragma unroll
    for (int mt = 0; mt < 2; ++mt)
        #pragma unroll
        for (int nt = 0; nt < 4; ++nt) {
            float2 v01 = make_float2(acc[mt][nt][0], acc[mt][nt][1]);
            float2 v23 = make_float2(acc[mt][nt][2], acc[mt][nt][3]);
            *(float2*)(C + (size_t)(r0 + mt * 16) * N_ + c0 + nt * 8)     = v01;
            *(float2*)(C + (size_t)(r0 + mt * 16 + 8) * N_ + c0 + nt * 8) = v23;
        }

    // ---- mirror tile via smem transpose (coalesced write-out) ----
    if (ti != tj) {
        float* T = (float*)smem;          // [128][132] floats (67584 B)
        int rl = wm * 32 + (lane >> 2);
        int cl = wn * 32 + (lane & 3) * 2;
        #pragma unroll
        for (int mt = 0; mt < 2; ++mt)
            #pragma unroll
            for (int nt = 0; nt < 4; ++nt) {
                int rr = rl + mt * 16;
                int cc = cl + nt * 8;
                T[(size_t)(cc + 0) * 132 + rr]     = acc[mt][nt][0];
                T[(size_t)(cc + 1) * 132 + rr]     = acc[mt][nt][1];
                T[(size_t)(cc + 0) * 132 + rr + 8] = acc[mt][nt][2];
                T[(size_t)(cc + 1) * 132 + rr + 8] = acc[mt][nt][3];
            }
        __syncthreads();
        int jb = tj * 128, ib = ti * 128;
        #pragma unroll
        for (int q = 0; q < 8; ++q) {
            int uu = q * 512 + tid;       // 0..4095
            int r = uu >> 5;
            int c4 = uu & 31;
            float4 v = *(float4*)&T[(size_t)r * 132 + c4 * 4];
            *(float4*)(C + (size_t)(jb + r) * N_ + ib + c4 * 4) = v;
        }
    }
}

// ---------------------------------------------------------------------------
// Kernel 3: per-row top-32 + symmetric atomic scatter.
// Winner invalidation uses unrolled static-index predicated writes so v[16]
// stays register-resident (no local-memory demotion). Selection semantics
// identical to R6/R7.
// ---------------------------------------------------------------------------
__global__ void __launch_bounds__(256) topk_scatter_kernel(float* __restrict__ out) {
    int row = blockIdx.x;
    int b = row >> 12;
    int i = row & (N_ - 1);
    const float* srow = g_sim + (size_t)b * N_ * N_ + (size_t)i * N_;
    int t = threadIdx.x;
    int lane = t & 31, warp = t >> 5;

    const float NEG_INF = __int_as_float(0xff800000);

    float v[16];
    #pragma unroll
    for (int q = 0; q < 16; q++) v[q] = srow[warp * 512 + q * 32 + lane];

    __shared__ float cV[256];
    __shared__ int   cI[256];

    // ---- phase 1: per-warp top-32 (register-resident, no block syncs) ----
    for (int r = 0; r < K_; r++) {
        float bv = v[0]; int bq = 0;
        #pragma unroll
        for (int q = 1; q < 16; q++)
            if (v[q] > bv) { bv = v[q]; bq = q; }
        int bix = warp * 512 + bq * 32 + lane;

        #pragma unroll
        for (int o = 16; o; o >>= 1) {
            float ov = __shfl_xor_sync(0xffffffffu, bv, o);
            int   oi = __shfl_xor_sync(0xffffffffu, bix, o);
            if (ov > bv || (ov == bv && oi < bix)) { bv = ov; bix = oi; }
        }
        if (lane == 0) { cV[warp * 32 + r] = bv; cI[warp * 32 + r] = bix; }

        // invalidate winner: static indices only, predicated on warp-uniform wq/wl
        int wl = bix & 31;
        int wq = (bix >> 5) & 15;
        #pragma unroll
        for (int q = 0; q < 16; q++)
            if (q == wq && lane == wl) v[q] = NEG_INF;
    }
    __syncthreads();

    // ---- phase 2: warp 0 merges 256 candidates -> top-32 ----
    __shared__ float sV[K_];
    __shared__ int   sI[K_];
    if (warp == 0) {
        float cv[8]; int ci[8];
        #pragma unroll
        for (int j = 0; j < 8; j++) { cv[j] = cV[j * 32 + lane]; ci[j] = cI[j * 32 + lane]; }

        for (int r = 0; r < K_; r++) {
            float bv = cv[0]; int bi = ci[0];
            #pragma unroll
            for (int j = 1; j < 8; j++)
                if (cv[j] > bv || (cv[j] == bv && ci[j] < bi)) { bv = cv[j]; bi = ci[j]; }

            #pragma unroll
            for (int o = 16; o; o >>= 1) {
                float ov = __shfl_xor_sync(0xffffffffu, bv, o);
                int   oi = __shfl_xor_sync(0xffffffffu, bi, o);
                if (ov > bv || (ov == bv && oi < bi)) { bv = ov; bi = oi; }
            }
            if (lane == 0) { sV[r] = bv; sI[r] = bi; }
            #pragma unroll
            for (int j = 0; j < 8; j++)
                if (ci[j] == bi) cv[j] = NEG_INF;
        }
    }
    __syncthreads();

    if (t < K_) {
        float val = 0.5f * sV[t];
        int j = sI[t];
        float* ob = out + (size_t)b * N_ * N_;
        atomicAdd(ob + (size_t)i * N_ + j, val);
        atomicAdd(ob + (size_t)j * N_ + i, val);
    }
}

// ---------------------------------------------------------------------------
extern "C" void kernel_launch(void* const* d_in, const int* in_sizes, int n_in,
                              void* d_out, int out_size) {
    const float* x = (const float*)d_in[0];
    float* out = (float*)d_out;

    cudaFuncSetAttribute(gemm_hmma_kernel,
                         cudaFuncAttributeMaxDynamicSharedMemorySize, SMEM_TOTAL);

    cudaMemsetAsync(out, 0, (size_t)out_size * sizeof(float));
    normalize_kernel<<<B_ * N_, 128>>>(x);
    gemm_hmma_kernel<<<B_ * PAIRS, 512, SMEM_TOTAL>>>();
    topk_scatter_kernel<<<B_ * N_, 256>>>(out);
}

// round 9
// speedup vs baseline: 2.2004x; 2.2004x over previous
#include <cuda_runtime.h>
#include <cuda_fp16.h>
#include <cstdint>

// Problem constants
#define B_ 4
#define N_ 4096
#define D_ 512
#define K_ 32
#define TILES 32            // N_/128
#define PAIRS 528           // TILES*(TILES+1)/2

// Scratch (device globals — no runtime allocation allowed)
__device__ __align__(128) __half g_h[(size_t)B_ * N_ * D_];           // 16 MB
__device__ __align__(128) __half g_l[(size_t)B_ * N_ * D_];           // 16 MB
__device__ __align__(128) float g_sim[(size_t)B_ * N_ * N_];          // 268 MB

// ---------------------------------------------------------------------------
// Portable PTX helpers (compute_103-safe)
// ---------------------------------------------------------------------------
__device__ __forceinline__ uint32_t smem_u32(const void* p) {
    uint32_t a;
    asm("{ .reg .u64 t; cvta.to.shared.u64 t, %1; cvt.u32.u64 %0, t; }"
        : "=r"(a) : "l"(p));
    return a;
}

#define SWZ(off) ((off) ^ (((off) >> 3) & 0x70))

#define CP_ASYNC16(dst_u32, src_ptr) \
    asm volatile("cp.async.cg.shared.global [%0], [%1], 16;" \
                 :: "r"(dst_u32), "l"(src_ptr) : "memory")
#define CP_COMMIT() asm volatile("cp.async.commit_group;" ::: "memory")
#define CP_WAIT(n)  asm volatile("cp.async.wait_group %0;" :: "n"(n) : "memory")

#define LDSM_X4(r0, r1, r2, r3, addr) \
    asm volatile("ldmatrix.sync.aligned.m8n8.x4.shared.b16 {%0,%1,%2,%3}, [%4];" \
                 : "=r"(r0), "=r"(r1), "=r"(r2), "=r"(r3) : "r"(addr))

#define MMA16816F16(c, a, b) \
    asm volatile("mma.sync.aligned.m16n8k16.row.col.f32.f16.f16.f32 " \
                 "{%0,%1,%2,%3}, {%4,%5,%6,%7}, {%8,%9}, {%0,%1,%2,%3};" \
                 : "+f"((c)[0]), "+f"((c)[1]), "+f"((c)[2]), "+f"((c)[3]) \
                 : "r"((a)[0]), "r"((a)[1]), "r"((a)[2]), "r"((a)[3]), \
                   "r"((b)[0]), "r"((b)[1]))

// ---------------------------------------------------------------------------
// Kernel 1: row L2-normalization + fp16 2-limb split (h + l ~ 22+ bits).
// (unchanged from R6)
// ---------------------------------------------------------------------------
__global__ void __launch_bounds__(128) normalize_kernel(const float* __restrict__ x) {
    int row = blockIdx.x;
    const float* xr = x + (size_t)row * D_;
    int t = threadIdx.x;

    float4 v = ((const float4*)xr)[t];
    float ss = v.x * v.x + v.y * v.y + v.z * v.z + v.w * v.w;
    #pragma unroll
    for (int o = 16; o; o >>= 1) ss += __shfl_xor_sync(0xffffffffu, ss, o);

    __shared__ float wsum[4];
    if ((t & 31) == 0) wsum[t >> 5] = ss;
    __syncthreads();
    float total = wsum[0] + wsum[1] + wsum[2] + wsum[3];
    float scale = 1.0f / fmaxf(sqrtf(total), 1e-12f);

    float xn[4] = {v.x * scale, v.y * scale, v.z * scale, v.w * scale};
    unsigned short hs[4], ls[4];
    #pragma unroll
    for (int q = 0; q < 4; q++) {
        __half h = __float2half_rn(xn[q]);
        float r1 = xn[q] - __half2float(h);
        __half l = __float2half_rn(r1);
        hs[q] = __half_as_ushort(h);
        ls[q] = __half_as_ushort(l);
    }
    uint2 hp, lp;
    hp.x = (uint32_t)hs[0] | ((uint32_t)hs[1] << 16);
    hp.y = (uint32_t)hs[2] | ((uint32_t)hs[3] << 16);
    lp.x = (uint32_t)ls[0] | ((uint32_t)ls[1] << 16);
    lp.y = (uint32_t)ls[2] | ((uint32_t)ls[3] << 16);
    ((uint2*)(g_h + (size_t)row * D_))[t] = hp;
    ((uint2*)(g_l + (size_t)row * D_))[t] = lp;
}

// ---------------------------------------------------------------------------
// Kernel 2: symmetric batched GEMM, fp16 2-limb 3-pass on mma.sync (HMMA).
// EXACT R6 version (measured best). g_sim bitwise identical to R6.
// ---------------------------------------------------------------------------
#define CHUNK_BYTES 16384                 // 128 rows x 64 fp16 (128B/row)
#define BUF_BYTES   (4 * CHUNK_BYTES)     // Ah, Al, Bh, Bl = 64 KB
#define SMEM_TOTAL  (2 * BUF_BYTES)       // 128 KB; transpose area reuses it

__global__ void __launch_bounds__(512, 1) gemm_hmma_kernel() {
    extern __shared__ __align__(1024) char smem[];
    uint32_t sbase = smem_u32(smem);
    int tid = threadIdx.x;
    int wid = tid >> 5;
    int lane = tid & 31;

    int bidx = blockIdx.x;
    int b = bidx / PAIRS;
    int u = bidx % PAIRS;
    int ti = 0;
    while (u >= TILES - ti) { u -= TILES - ti; ti++; }
    int tj = ti + u;                      // tj >= ti

    size_t aoff = ((size_t)b * N_ + (size_t)ti * 128) * D_;
    size_t boff = ((size_t)b * N_ + (size_t)tj * 128) * D_;
    const __half* srcs[4] = {
        g_h + aoff, g_l + aoff,           // A limbs
        g_h + boff, g_l + boff            // B limbs
    };

    int wm = wid & 3;                     // 4 warps in M (32 rows each)
    int wn = wid >> 2;                    // 4 warps in N (32 cols each)

    float acc[2][4][4];
    #pragma unroll
    for (int mt = 0; mt < 2; mt++)
        #pragma unroll
        for (int nt = 0; nt < 4; nt++)
            #pragma unroll
            for (int q = 0; q < 4; q++) acc[mt][nt][q] = 0.0f;

    auto load_chunk = [&](int kc, int buf) {
        uint32_t bufoff = sbase + buf * BUF_BYTES;
        #pragma unroll
        for (int tile = 0; tile < 4; ++tile) {
            #pragma unroll
            for (int q = 0; q < 2; ++q) {
                int uu = q * 512 + tid;           // 0..1023
                int row = uu >> 3;
                int seg = uu & 7;
                const __half* src = srcs[tile] + (size_t)row * D_ + kc * 64 + seg * 8;
                uint32_t dst = bufoff + tile * CHUNK_BYTES + SWZ(row * 128 + seg * 16);
                CP_ASYNC16(dst, src);
            }
        }
    };

    int lr = lane & 15;
    int lc = (lane >> 4) * 16;

    auto compute_chunk = [&](int buf) {
        uint32_t aH = sbase + buf * BUF_BYTES;
        uint32_t aL = aH + CHUNK_BYTES;
        uint32_t bH = aH + 2 * CHUNK_BYTES;
        uint32_t bL = aH + 3 * CHUNK_BYTES;
        #pragma unroll
        for (int ks = 0; ks < 4; ++ks) {
            int kb = ks * 32;
            uint32_t ah[2][4], al[2][4];
            uint32_t bh[4][2], bl[4][2];
            #pragma unroll
            for (int mt = 0; mt < 2; ++mt) {
                int row = wm * 32 + mt * 16 + lr;
                uint32_t off = SWZ(row * 128 + kb + lc);
                LDSM_X4(ah[mt][0], ah[mt][1], ah[mt][2], ah[mt][3], aH + off);
                LDSM_X4(al[mt][0], al[mt][1], al[mt][2], al[mt][3], aL + off);
            }
            #pragma unroll
            for (int h = 0; h < 2; ++h) {
                int row = wn * 32 + h * 16 + lr;
                uint32_t off = SWZ(row * 128 + kb + lc);
                uint32_t r0, r1, r2, r3;
                LDSM_X4(r0, r1, r2, r3, bH + off);
                bh[2 * h + 0][0] = r0; bh[2 * h + 0][1] = r2;
                bh[2 * h + 1][0] = r1; bh[2 * h + 1][1] = r3;
                LDSM_X4(r0, r1, r2, r3, bL + off);
                bl[2 * h + 0][0] = r0; bl[2 * h + 0][1] = r2;
                bl[2 * h + 1][0] = r1; bl[2 * h + 1][1] = r3;
            }
            #pragma unroll
            for (int mt = 0; mt < 2; ++mt)
                #pragma unroll
                for (int nt = 0; nt < 4; ++nt) {
                    MMA16816F16(acc[mt][nt], ah[mt], bh[nt]);   // hh
                    MMA16816F16(acc[mt][nt], ah[mt], bl[nt]);   // hl
                    MMA16816F16(acc[mt][nt], al[mt], bh[nt]);   // lh
                }
        }
    };

    // ---- pipelined main loop over 8 K-chunks (R6 structure) ----
    const int NCHUNK = D_ / 64;
    load_chunk(0, 0); CP_COMMIT();
    for (int kc = 0; kc < NCHUNK; ++kc) {
        if (kc + 1 < NCHUNK) {
            load_chunk(kc + 1, (kc + 1) & 1); CP_COMMIT();
            CP_WAIT(1);
        } else {
            CP_WAIT(0);
        }
        __syncthreads();
        compute_chunk(kc & 1);
        __syncthreads();                  // before next load overwrites other buf
    }

    // ---- epilogue: direct tile (coalesced float2 per fragment row) ----
    float* C = g_sim + (size_t)b * N_ * N_;
    int r0 = ti * 128 + wm * 32 + (lane >> 2);
    int c0 = tj * 128 + wn * 32 + (lane & 3) * 2;
    #pragma unroll
    for (int mt = 0; mt < 2; ++mt)
        #pragma unroll
        for (int nt = 0; nt < 4; ++nt) {
            float2 v01 = make_float2(acc[mt][nt][0], acc[mt][nt][1]);
            float2 v23 = make_float2(acc[mt][nt][2], acc[mt][nt][3]);
            *(float2*)(C + (size_t)(r0 + mt * 16) * N_ + c0 + nt * 8)     = v01;
            *(float2*)(C + (size_t)(r0 + mt * 16 + 8) * N_ + c0 + nt * 8) = v23;
        }

    // ---- mirror tile via smem transpose (coalesced write-out) ----
    if (ti != tj) {
        float* T = (float*)smem;          // [128][132] floats (67584 B)
        int rl = wm * 32 + (lane >> 2);
        int cl = wn * 32 + (lane & 3) * 2;
        #pragma unroll
        for (int mt = 0; mt < 2; ++mt)
            #pragma unroll
            for (int nt = 0; nt < 4; ++nt) {
                int rr = rl + mt * 16;
                int cc = cl + nt * 8;
                T[(size_t)(cc + 0) * 132 + rr]     = acc[mt][nt][0];
                T[(size_t)(cc + 1) * 132 + rr]     = acc[mt][nt][1];
                T[(size_t)(cc + 0) * 132 + rr + 8] = acc[mt][nt][2];
                T[(size_t)(cc + 1) * 132 + rr + 8] = acc[mt][nt][3];
            }
        __syncthreads();
        int jb = tj * 128, ib = ti * 128;
        #pragma unroll
        for (int q = 0; q < 8; ++q) {
            int uu = q * 512 + tid;       // 0..4095
            int r = uu >> 5;
            int c4 = uu & 31;
            float4 v = *(float4*)&T[(size_t)r * 132 + c4 * 4];
            *(float4*)(C + (size_t)(jb + r) * N_ + ib + c4 * 4) = v;
        }
    }
}

// ---------------------------------------------------------------------------
// Kernel 3: per-row top-32 via THRESHOLD CANDIDATE PRUNING + exact fallback.
// Values are cosine sims of normalized gaussians: rank-32 value ~0.107,
// so candidates = {v > 0.09} (expected ~86 per row). Exact top-k over the
// candidate set equals full top-k whenever count >= 32 (all top-32 values
// exceed T). If count < 32 or count > capacity: full R6-style fallback.
// Output identical to R6 in all cases.
// ---------------------------------------------------------------------------
#define THRESH 0.09f
#define CAND_MAX 256

__global__ void __launch_bounds__(256) topk_scatter_kernel(float* __restrict__ out) {
    int row = blockIdx.x;
    int b = row >> 12;
    int i = row & (N_ - 1);
    const float* srow = g_sim + (size_t)b * N_ * N_ + (size_t)i * N_;
    int t = threadIdx.x;
    int lane = t & 31, warp = t >> 5;

    const float NEG_INF = __int_as_float(0xff800000);

    __shared__ float cV[CAND_MAX];
    __shared__ int   cI[CAND_MAX];
    __shared__ int   scnt;
    __shared__ float sV[K_];
    __shared__ int   sI[K_];
    if (t == 0) scnt = 0;
    __syncthreads();

    // coalesced row load (same layout as R6)
    float v[16];
    #pragma unroll
    for (int q = 0; q < 16; q++) v[q] = srow[warp * 512 + q * 32 + lane];

    // ---- candidate extraction: warp-aggregated ballot compaction ----
    #pragma unroll
    for (int q = 0; q < 16; q++) {
        bool p = v[q] > THRESH;
        unsigned mask = __ballot_sync(0xffffffffu, p);
        if (mask) {
            int base = 0;
            if (lane == 0) base = atomicAdd(&scnt, __popc(mask));
            base = __shfl_sync(0xffffffffu, base, 0);
            if (p) {
                int pos = base + __popc(mask & ((1u << lane) - 1));
                if (pos < CAND_MAX) {
                    cV[pos] = v[q];
                    cI[pos] = warp * 512 + q * 32 + lane;
                }
            }
        }
    }
    __syncthreads();
    int cnt = scnt;

    if (cnt >= K_ && cnt <= CAND_MAX) {
        // ---- fast path: one warp, exact top-32 over <=256 candidates ----
        if (warp == 0) {
            float cv[8]; int ci[8];
            #pragma unroll
            for (int j = 0; j < 8; j++) {
                int idx = j * 32 + lane;
                bool ok = idx < cnt;
                cv[j] = ok ? cV[idx] : NEG_INF;
                ci[j] = ok ? cI[idx] : 0x7fffffff;
            }
            for (int r = 0; r < K_; r++) {
                float bv = cv[0]; int bi = ci[0];
                #pragma unroll
                for (int j = 1; j < 8; j++)
                    if (cv[j] > bv || (cv[j] == bv && ci[j] < bi)) { bv = cv[j]; bi = ci[j]; }
                #pragma unroll
                for (int o = 16; o; o >>= 1) {
                    float ov = __shfl_xor_sync(0xffffffffu, bv, o);
                    int   oi = __shfl_xor_sync(0xffffffffu, bi, o);
                    if (ov > bv || (ov == bv && oi < bi)) { bv = ov; bi = oi; }
                }
                if (lane == 0) { sV[r] = bv; sI[r] = bi; }
                #pragma unroll
                for (int j = 0; j < 8; j++)
                    if (ci[j] == bi) cv[j] = NEG_INF;
            }
        }
    } else {
        // ---- fallback: full R6 method (statistically ~never taken) ----
        for (int r = 0; r < K_; r++) {
            float bv = v[0]; int bq = 0;
            #pragma unroll
            for (int q = 1; q < 16; q++)
                if (v[q] > bv) { bv = v[q]; bq = q; }
            int bix = warp * 512 + bq * 32 + lane;

            #pragma unroll
            for (int o = 16; o; o >>= 1) {
                float ov = __shfl_xor_sync(0xffffffffu, bv, o);
                int   oi = __shfl_xor_sync(0xffffffffu, bix, o);
                if (ov > bv || (ov == bv && oi < bix)) { bv = ov; bix = oi; }
            }
            if (lane == 0) { cV[warp * 32 + r] = bv; cI[warp * 32 + r] = bix; }
            if ((bix & 31) == lane) v[(bix >> 5) & 15] = NEG_INF;
            __syncwarp();
        }
        __syncthreads();
        if (warp == 0) {
            float cv[8]; int ci[8];
            #pragma unroll
            for (int j = 0; j < 8; j++) { cv[j] = cV[j * 32 + lane]; ci[j] = cI[j * 32 + lane]; }
            for (int r = 0; r < K_; r++) {
                float bv = cv[0]; int bi = ci[0];
                #pragma unroll
                for (int j = 1; j < 8; j++)
                    if (cv[j] > bv || (cv[j] == bv && ci[j] < bi)) { bv = cv[j]; bi = ci[j]; }
                #pragma unroll
                for (int o = 16; o; o >>= 1) {
                    float ov = __shfl_xor_sync(0xffffffffu, bv, o);
                    int   oi = __shfl_xor_sync(0xffffffffu, bi, o);
                    if (ov > bv || (ov == bv && oi < bi)) { bv = ov; bi = oi; }
                }
                if (lane == 0) { sV[r] = bv; sI[r] = bi; }
                #pragma unroll
                for (int j = 0; j < 8; j++)
                    if (ci[j] == bi) cv[j] = NEG_INF;
            }
        }
    }
    __syncthreads();

    if (t < K_) {
        float val = 0.5f * sV[t];
        int j = sI[t];
        float* ob = out + (size_t)b * N_ * N_;
        atomicAdd(ob + (size_t)i * N_ + j, val);
        atomicAdd(ob + (size_t)j * N_ + i, val);
    }
}

// ---------------------------------------------------------------------------
extern "C" void kernel_launch(void* const* d_in, const int* in_sizes, int n_in,
                              void* d_out, int out_size) {
    const float* x = (const float*)d_in[0];
    float* out = (float*)d_out;

    cudaFuncSetAttribute(gemm_hmma_kernel,
                         cudaFuncAttributeMaxDynamicSharedMemorySize, SMEM_TOTAL);

    cudaMemsetAsync(out, 0, (size_t)out_size * sizeof(float));
    normalize_kernel<<<B_ * N_, 128>>>(x);
    gemm_hmma_kernel<<<B_ * PAIRS, 512, SMEM_TOTAL>>>();
    topk_scatter_kernel<<<B_ * N_, 256>>>(out);
}

// round 10
// speedup vs baseline: 2.2709x; 1.0320x over previous
#include <cuda_runtime.h>
#include <cuda_fp16.h>
#include <cstdint>

// Problem constants
#define B_ 4
#define N_ 4096
#define D_ 512
#define K_ 32
#define TILES 32            // N_/128
#define PAIRS 528           // TILES*(TILES+1)/2

// Scratch (device globals — no runtime allocation allowed)
__device__ __align__(128) __half g_h[(size_t)B_ * N_ * D_];           // 16 MB
__device__ __align__(128) __half g_l[(size_t)B_ * N_ * D_];           // 16 MB
__device__ __align__(128) float g_sim[(size_t)B_ * N_ * N_];          // 268 MB

// ---------------------------------------------------------------------------
// Portable PTX helpers (compute_103-safe)
// ---------------------------------------------------------------------------
__device__ __forceinline__ uint32_t smem_u32(const void* p) {
    uint32_t a;
    asm("{ .reg .u64 t; cvta.to.shared.u64 t, %1; cvt.u32.u64 %0, t; }"
        : "=r"(a) : "l"(p));
    return a;
}

#define SWZ(off) ((off) ^ (((off) >> 3) & 0x70))

#define CP_ASYNC16(dst_u32, src_ptr) \
    asm volatile("cp.async.cg.shared.global [%0], [%1], 16;" \
                 :: "r"(dst_u32), "l"(src_ptr) : "memory")
#define CP_COMMIT() asm volatile("cp.async.commit_group;" ::: "memory")
#define CP_WAIT(n)  asm volatile("cp.async.wait_group %0;" :: "n"(n) : "memory")

#define LDSM_X4(r0, r1, r2, r3, addr) \
    asm volatile("ldmatrix.sync.aligned.m8n8.x4.shared.b16 {%0,%1,%2,%3}, [%4];" \
                 : "=r"(r0), "=r"(r1), "=r"(r2), "=r"(r3) : "r"(addr))

#define MMA16816F16(c, a, b) \
    asm volatile("mma.sync.aligned.m16n8k16.row.col.f32.f16.f16.f32 " \
                 "{%0,%1,%2,%3}, {%4,%5,%6,%7}, {%8,%9}, {%0,%1,%2,%3};" \
                 : "+f"((c)[0]), "+f"((c)[1]), "+f"((c)[2]), "+f"((c)[3]) \
                 : "r"((a)[0]), "r"((a)[1]), "r"((a)[2]), "r"((a)[3]), \
                   "r"((b)[0]), "r"((b)[1]))

// ---------------------------------------------------------------------------
// Kernel 1: row L2-normalization + fp16 2-limb split (unchanged).
// ---------------------------------------------------------------------------
__global__ void __launch_bounds__(128) normalize_kernel(const float* __restrict__ x) {
    int row = blockIdx.x;
    const float* xr = x + (size_t)row * D_;
    int t = threadIdx.x;

    float4 v = ((const float4*)xr)[t];
    float ss = v.x * v.x + v.y * v.y + v.z * v.z + v.w * v.w;
    #pragma unroll
    for (int o = 16; o; o >>= 1) ss += __shfl_xor_sync(0xffffffffu, ss, o);

    __shared__ float wsum[4];
    if ((t & 31) == 0) wsum[t >> 5] = ss;
    __syncthreads();
    float total = wsum[0] + wsum[1] + wsum[2] + wsum[3];
    float scale = 1.0f / fmaxf(sqrtf(total), 1e-12f);

    float xn[4] = {v.x * scale, v.y * scale, v.z * scale, v.w * scale};
    unsigned short hs[4], ls[4];
    #pragma unroll
    for (int q = 0; q < 4; q++) {
        __half h = __float2half_rn(xn[q]);
        float r1 = xn[q] - __half2float(h);
        __half l = __float2half_rn(r1);
        hs[q] = __half_as_ushort(h);
        ls[q] = __half_as_ushort(l);
    }
    uint2 hp, lp;
    hp.x = (uint32_t)hs[0] | ((uint32_t)hs[1] << 16);
    hp.y = (uint32_t)hs[2] | ((uint32_t)hs[3] << 16);
    lp.x = (uint32_t)ls[0] | ((uint32_t)ls[1] << 16);
    lp.y = (uint32_t)ls[2] | ((uint32_t)ls[3] << 16);
    ((uint2*)(g_h + (size_t)row * D_))[t] = hp;
    ((uint2*)(g_l + (size_t)row * D_))[t] = lp;
}

// ---------------------------------------------------------------------------
// Kernel 2: symmetric batched GEMM, fp16 2-limb 3-pass on mma.sync (HMMA).
// 2 CTAs/SM: 256 threads (8 warps 2x4, warp tile 64x32), SINGLE 64KB smem
// buffer (cross-CTA overlap instead of intra-CTA double buffering).
// Per-element MMA contribution order identical to R6/R9 -> g_sim bitwise same.
// ---------------------------------------------------------------------------
#define CHUNK_BYTES 16384                 // 128 rows x 64 fp16 (128B/row)
#define SMEM_TOTAL  67584                 // max(4*CHUNK=65536, transpose 128*132*4)

__global__ void __launch_bounds__(256, 2) gemm_hmma_kernel() {
    extern __shared__ __align__(1024) char smem[];
    uint32_t sbase = smem_u32(smem);
    int tid = threadIdx.x;
    int wid = tid >> 5;
    int lane = tid & 31;

    int bidx = blockIdx.x;
    int b = bidx / PAIRS;
    int u = bidx % PAIRS;
    int ti = 0;
    while (u >= TILES - ti) { u -= TILES - ti; ti++; }
    int tj = ti + u;                      // tj >= ti

    size_t aoff = ((size_t)b * N_ + (size_t)ti * 128) * D_;
    size_t boff = ((size_t)b * N_ + (size_t)tj * 128) * D_;
    const __half* srcs[4] = {
        g_h + aoff, g_l + aoff,           // A limbs
        g_h + boff, g_l + boff            // B limbs
    };

    int wm = wid & 1;                     // 2 warps in M (64 rows each)
    int wn = wid >> 1;                    // 4 warps in N (32 cols each)

    float acc[4][4][4];
    #pragma unroll
    for (int mt = 0; mt < 4; mt++)
        #pragma unroll
        for (int nt = 0; nt < 4; nt++)
            #pragma unroll
            for (int q = 0; q < 4; q++) acc[mt][nt][q] = 0.0f;

    auto load_chunk = [&](int kc) {
        #pragma unroll
        for (int tile = 0; tile < 4; ++tile) {
            #pragma unroll
            for (int q = 0; q < 4; ++q) {
                int uu = q * 256 + tid;           // 0..1023
                int row = uu >> 3;
                int seg = uu & 7;
                const __half* src = srcs[tile] + (size_t)row * D_ + kc * 64 + seg * 8;
                uint32_t dst = sbase + tile * CHUNK_BYTES + SWZ(row * 128 + seg * 16);
                CP_ASYNC16(dst, src);
            }
        }
    };

    int lr = lane & 15;
    int lc = (lane >> 4) * 16;

    auto compute_chunk = [&]() {
        uint32_t aH = sbase;
        uint32_t aL = aH + CHUNK_BYTES;
        uint32_t bH = aH + 2 * CHUNK_BYTES;
        uint32_t bL = aH + 3 * CHUNK_BYTES;
        #pragma unroll
        for (int ks = 0; ks < 4; ++ks) {
            int kb = ks * 32;
            uint32_t bh[4][2], bl[4][2];
            #pragma unroll
            for (int h = 0; h < 2; ++h) {
                int row = wn * 32 + h * 16 + lr;
                uint32_t off = SWZ(row * 128 + kb + lc);
                uint32_t r0, r1, r2, r3;
                LDSM_X4(r0, r1, r2, r3, bH + off);
                bh[2 * h + 0][0] = r0; bh[2 * h + 0][1] = r2;
                bh[2 * h + 1][0] = r1; bh[2 * h + 1][1] = r3;
                LDSM_X4(r0, r1, r2, r3, bL + off);
                bl[2 * h + 0][0] = r0; bl[2 * h + 0][1] = r2;
                bl[2 * h + 1][0] = r1; bl[2 * h + 1][1] = r3;
            }
            #pragma unroll
            for (int mt = 0; mt < 4; ++mt) {
                int row = wm * 64 + mt * 16 + lr;
                uint32_t off = SWZ(row * 128 + kb + lc);
                uint32_t ah[4], al[4];
                LDSM_X4(ah[0], ah[1], ah[2], ah[3], aH + off);
                LDSM_X4(al[0], al[1], al[2], al[3], aL + off);
                #pragma unroll
                for (int nt = 0; nt < 4; ++nt) {
                    MMA16816F16(acc[mt][nt], ah, bh[nt]);   // hh
                    MMA16816F16(acc[mt][nt], ah, bl[nt]);   // hl
                    MMA16816F16(acc[mt][nt], al, bh[nt]);   // lh
                }
            }
        }
    };

    // ---- main loop: single buffer; cross-CTA overlap hides load latency ----
    const int NCHUNK = D_ / 64;
    for (int kc = 0; kc < NCHUNK; ++kc) {
        load_chunk(kc);
        CP_COMMIT();
        CP_WAIT(0);
        __syncthreads();
        compute_chunk();
        __syncthreads();                  // before next load overwrites buffer
    }

    // ---- epilogue: direct tile (coalesced float2 per fragment row) ----
    float* C = g_sim + (size_t)b * N_ * N_;
    int r0 = ti * 128 + wm * 64 + (lane >> 2);
    int c0 = tj * 128 + wn * 32 + (lane & 3) * 2;
    #pragma unroll
    for (int mt = 0; mt < 4; ++mt)
        #pragma unroll
        for (int nt = 0; nt < 4; ++nt) {
            float2 v01 = make_float2(acc[mt][nt][0], acc[mt][nt][1]);
            float2 v23 = make_float2(acc[mt][nt][2], acc[mt][nt][3]);
            *(float2*)(C + (size_t)(r0 + mt * 16) * N_ + c0 + nt * 8)     = v01;
            *(float2*)(C + (size_t)(r0 + mt * 16 + 8) * N_ + c0 + nt * 8) = v23;
        }

    // ---- mirror tile via smem transpose (coalesced write-out) ----
    if (ti != tj) {
        float* T = (float*)smem;          // [128][132] floats (67584 B)
        int rl = wm * 64 + (lane >> 2);
        int cl = wn * 32 + (lane & 3) * 2;
        #pragma unroll
        for (int mt = 0; mt < 4; ++mt)
            #pragma unroll
            for (int nt = 0; nt < 4; ++nt) {
                int rr = rl + mt * 16;
                int cc = cl + nt * 8;
                T[(size_t)(cc + 0) * 132 + rr]     = acc[mt][nt][0];
                T[(size_t)(cc + 1) * 132 + rr]     = acc[mt][nt][1];
                T[(size_t)(cc + 0) * 132 + rr + 8] = acc[mt][nt][2];
                T[(size_t)(cc + 1) * 132 + rr + 8] = acc[mt][nt][3];
            }
        __syncthreads();
        int jb = tj * 128, ib = ti * 128;
        #pragma unroll
        for (int q = 0; q < 16; ++q) {
            int uu = q * 256 + tid;       // 0..4095
            int r = uu >> 5;
            int c4 = uu & 31;
            float4 v = *(float4*)&T[(size_t)r * 132 + c4 * 4];
            *(float4*)(C + (size_t)(jb + r) * N_ + ib + c4 * 4) = v;
        }
    }
}

// ---------------------------------------------------------------------------
// Kernel 3: threshold-pruned top-32 + exact fallback (unchanged from R9).
// ---------------------------------------------------------------------------
#define THRESH 0.09f
#define CAND_MAX 256

__global__ void __launch_bounds__(256) topk_scatter_kernel(float* __restrict__ out) {
    int row = blockIdx.x;
    int b = row >> 12;
    int i = row & (N_ - 1);
    const float* srow = g_sim + (size_t)b * N_ * N_ + (size_t)i * N_;
    int t = threadIdx.x;
    int lane = t & 31, warp = t >> 5;

    const float NEG_INF = __int_as_float(0xff800000);

    __shared__ float cV[CAND_MAX];
    __shared__ int   cI[CAND_MAX];
    __shared__ int   scnt;
    __shared__ float sV[K_];
    __shared__ int   sI[K_];
    if (t == 0) scnt = 0;
    __syncthreads();

    float v[16];
    #pragma unroll
    for (int q = 0; q < 16; q++) v[q] = srow[warp * 512 + q * 32 + lane];

    #pragma unroll
    for (int q = 0; q < 16; q++) {
        bool p = v[q] > THRESH;
        unsigned mask = __ballot_sync(0xffffffffu, p);
        if (mask) {
            int base = 0;
            if (lane == 0) base = atomicAdd(&scnt, __popc(mask));
            base = __shfl_sync(0xffffffffu, base, 0);
            if (p) {
                int pos = base + __popc(mask & ((1u << lane) - 1));
                if (pos < CAND_MAX) {
                    cV[pos] = v[q];
                    cI[pos] = warp * 512 + q * 32 + lane;
                }
            }
        }
    }
    __syncthreads();
    int cnt = scnt;

    if (cnt >= K_ && cnt <= CAND_MAX) {
        if (warp == 0) {
            float cv[8]; int ci[8];
            #pragma unroll
            for (int j = 0; j < 8; j++) {
                int idx = j * 32 + lane;
                bool ok = idx < cnt;
                cv[j] = ok ? cV[idx] : NEG_INF;
                ci[j] = ok ? cI[idx] : 0x7fffffff;
            }
            for (int r = 0; r < K_; r++) {
                float bv = cv[0]; int bi = ci[0];
                #pragma unroll
                for (int j = 1; j < 8; j++)
                    if (cv[j] > bv || (cv[j] == bv && ci[j] < bi)) { bv = cv[j]; bi = ci[j]; }
                #pragma unroll
                for (int o = 16; o; o >>= 1) {
                    float ov = __shfl_xor_sync(0xffffffffu, bv, o);
                    int   oi = __shfl_xor_sync(0xffffffffu, bi, o);
                    if (ov > bv || (ov == bv && oi < bi)) { bv = ov; bi = oi; }
                }
                if (lane == 0) { sV[r] = bv; sI[r] = bi; }
                #pragma unroll
                for (int j = 0; j < 8; j++)
                    if (ci[j] == bi) cv[j] = NEG_INF;
            }
        }
    } else {
        for (int r = 0; r < K_; r++) {
            float bv = v[0]; int bq = 0;
            #pragma unroll
            for (int q = 1; q < 16; q++)
                if (v[q] > bv) { bv = v[q]; bq = q; }
            int bix = warp * 512 + bq * 32 + lane;

            #pragma unroll
            for (int o = 16; o; o >>= 1) {
                float ov = __shfl_xor_sync(0xffffffffu, bv, o);
                int   oi = __shfl_xor_sync(0xffffffffu, bix, o);
                if (ov > bv || (ov == bv && oi < bix)) { bv = ov; bix = oi; }
            }
            if (lane == 0) { cV[warp * 32 + r] = bv; cI[warp * 32 + r] = bix; }
            if ((bix & 31) == lane) v[(bix >> 5) & 15] = NEG_INF;
            __syncwarp();
        }
        __syncthreads();
        if (warp == 0) {
            float cv[8]; int ci[8];
            #pragma unroll
            for (int j = 0; j < 8; j++) { cv[j] = cV[j * 32 + lane]; ci[j] = cI[j * 32 + lane]; }
            for (int r = 0; r < K_; r++) {
                float bv = cv[0]; int bi = ci[0];
                #pragma unroll
                for (int j = 1; j < 8; j++)
                    if (cv[j] > bv || (cv[j] == bv && ci[j] < bi)) { bv = cv[j]; bi = ci[j]; }
                #pragma unroll
                for (int o = 16; o; o >>= 1) {
                    float ov = __shfl_xor_sync(0xffffffffu, bv, o);
                    int   oi = __shfl_xor_sync(0xffffffffu, bi, o);
                    if (ov > bv || (ov == bv && oi < bi)) { bv = ov; bi = oi; }
                }
                if (lane == 0) { sV[r] = bv; sI[r] = bi; }
                #pragma unroll
                for (int j = 0; j < 8; j++)
                    if (ci[j] == bi) cv[j] = NEG_INF;
            }
        }
    }
    __syncthreads();

    if (t < K_) {
        float val = 0.5f * sV[t];
        int j = sI[t];
        float* ob = out + (size_t)b * N_ * N_;
        atomicAdd(ob + (size_t)i * N_ + j, val);
        atomicAdd(ob + (size_t)j * N_ + i, val);
    }
}

// ---------------------------------------------------------------------------
extern "C" void kernel_launch(void* const* d_in, const int* in_sizes, int n_in,
                              void* d_out, int out_size) {
    const float* x = (const float*)d_in[0];
    float* out = (float*)d_out;

    cudaFuncSetAttribute(gemm_hmma_kernel,
                         cudaFuncAttributeMaxDynamicSharedMemorySize, SMEM_TOTAL);

    cudaMemsetAsync(out, 0, (size_t)out_size * sizeof(float));
    normalize_kernel<<<B_ * N_, 128>>>(x);
    gemm_hmma_kernel<<<B_ * PAIRS, 256, SMEM_TOTAL>>>();
    topk_scatter_kernel<<<B_ * N_, 256>>>(out);
}